// round 6
// baseline (speedup 1.0000x reference)
#include <cuda_runtime.h>
#include <cstdint>
#include <math.h>

typedef unsigned long long u64;

// ---------------------------------------------------------------------------
// Packed f32x2 helpers (Blackwell sm_103a)
// ---------------------------------------------------------------------------
__device__ __forceinline__ u64 ffma2(u64 a, u64 b, u64 c) {
    u64 d;
    asm("fma.rn.f32x2 %0, %1, %2, %3;" : "=l"(d) : "l"(a), "l"(b), "l"(c));
    return d;
}
__device__ __forceinline__ u64 pack2(float x, float y) {
    u64 r;
    asm("mov.b64 %0, {%1, %2};" : "=l"(r) : "f"(x), "f"(y));
    return r;
}
__device__ __forceinline__ float2 unpack2(u64 v) {
    float2 f;
    asm("mov.b64 {%0, %1}, %2;" : "=f"(f.x), "=f"(f.y) : "l"(v));
    return f;
}
__device__ __forceinline__ uint32_t smem_u32(const void* p) {
    uint32_t a;
    asm("{ .reg .u64 t; cvta.to.shared.u64 t, %1; cvt.u32.u64 %0, t; }"
        : "=r"(a) : "l"(p));
    return a;
}

// Accurate tanh via ex2.approx (rel err ~2^-22); tanhf under fast-math lowers
// to tanh.approx (abs err ~2^-11) and fails 1e-3 over 1024 recurrent steps.
__device__ __forceinline__ float tanh_acc(float x) {
    float e = __expf(2.0f * x);
    return 1.0f - 2.0f / (e + 1.0f);
}

// ---------------------------------------------------------------------------
// Phase 1: x_proj GEMM (unchanged; ~231us)
// ---------------------------------------------------------------------------
__global__ void __launch_bounds__(256) xproj_kernel(
    const float* __restrict__ X, const float* __restrict__ Wih,
    const float* __restrict__ bih, float* __restrict__ C)
{
    __shared__ __align__(16) float As[16][128];
    __shared__ __align__(16) float Bs[16][128];

    const int tid = threadIdx.x;
    const int tx  = tid & 15;
    const int ty  = tid >> 4;
    const int m0  = blockIdx.y * 128;
    const int n0  = blockIdx.x * 128;

    u64 acc[8][4];
#pragma unroll
    for (int m = 0; m < 8; m++)
#pragma unroll
        for (int n = 0; n < 4; n++) acc[m][n] = 0ull;

    for (int k0 = 0; k0 < 256; k0 += 16) {
#pragma unroll
        for (int i = 0; i < 2; i++) {
            int idx = tid + i * 256;
            int row = idx >> 2;
            int kq  = (idx & 3) << 2;
            float4 xa = *(const float4*)(X + (size_t)(m0 + row) * 256 + k0 + kq);
            As[kq + 0][row] = xa.x; As[kq + 1][row] = xa.y;
            As[kq + 2][row] = xa.z; As[kq + 3][row] = xa.w;
            float4 wa = *(const float4*)(Wih + (size_t)(n0 + row) * 256 + k0 + kq);
            Bs[kq + 0][row] = wa.x; Bs[kq + 1][row] = wa.y;
            Bs[kq + 2][row] = wa.z; Bs[kq + 3][row] = wa.w;
        }
        __syncthreads();

#pragma unroll
        for (int kk = 0; kk < 16; kk++) {
            float4 a0 = *(const float4*)&As[kk][ty * 8];
            float4 a1 = *(const float4*)&As[kk][ty * 8 + 4];
            float4 b0 = *(const float4*)&Bs[kk][tx * 8];
            float4 b1 = *(const float4*)&Bs[kk][tx * 8 + 4];
            u64 bb[4] = { pack2(b0.x, b0.y), pack2(b0.z, b0.w),
                          pack2(b1.x, b1.y), pack2(b1.z, b1.w) };
            float am[8] = { a0.x, a0.y, a0.z, a0.w, a1.x, a1.y, a1.z, a1.w };
#pragma unroll
            for (int m = 0; m < 8; m++) {
                u64 ad = pack2(am[m], am[m]);
#pragma unroll
                for (int n = 0; n < 4; n++) acc[m][n] = ffma2(ad, bb[n], acc[m][n]);
            }
        }
        __syncthreads();
    }

    const int nc = n0 + tx * 8;
    float4 bv0 = *(const float4*)(bih + nc);
    float4 bv1 = *(const float4*)(bih + nc + 4);
#pragma unroll
    for (int m = 0; m < 8; m++) {
        float2 r0 = unpack2(acc[m][0]), r1 = unpack2(acc[m][1]);
        float2 r2 = unpack2(acc[m][2]), r3 = unpack2(acc[m][3]);
        float* cp = C + (size_t)(m0 + ty * 8 + m) * 256 + nc;
        *(float4*)cp       = make_float4(r0.x + bv0.x, r0.y + bv0.y,
                                         r1.x + bv0.z, r1.y + bv0.w);
        *(float4*)(cp + 4) = make_float4(r2.x + bv1.x, r2.y + bv1.y,
                                         r3.x + bv1.z, r3.y + bv1.w);
    }
}

// ---------------------------------------------------------------------------
// Phase 2 (v6): R4 structure + single bulk-copy signaling per step.
//
// Cluster of 2 CTAs per batch; CTA r owns outputs/k-range J_r (h never
// crosses the cluster; weights fully register-resident, 64 u64/thread).
// Per step, senders (outputs in peer's range) STS partials to a local stage
// buffer, named-bar among the 4 sender warps, then ONE elected thread issues
// cp.async.bulk.shared::cluster (512B) -> peer recv buffer. The remote
// mbarrier receives ONE complete_tx (vs 32 st.async updates in R4, whose
// same-address SYNCS serialization is the suspected ~900cyc drain).
//
// Two parity barriers: barrier[p] serves steps t = p (mod 2), wait parity
// (t>>1)&1; re-arm for t+2 posted between wait(t) and __syncthreads(t).
// Deadlock-freedom chain (as proven in R4):
//   peer send(t+2) >= peer sync(t+1) >= peer wait(t+1) >= our send(t+1)
//   >= our sync(t) >= our expect(t+2).
// The same chain orders stage-buffer reuse after the peer's copy completes.
// ---------------------------------------------------------------------------
__device__ __forceinline__ void mbar_wait_cluster(uint32_t addr, uint32_t parity) {
    asm volatile(
        "{\n\t"
        ".reg .pred P;\n\t"
        "LAB_W_%=:\n\t"
        "mbarrier.try_wait.parity.acquire.cluster.shared::cta.b64 P, [%0], %1, 0x989680;\n\t"
        "@P bra.uni LAB_D_%=;\n\t"
        "bra.uni LAB_W_%=;\n\t"
        "LAB_D_%=:\n\t"
        "}"
        :: "r"(addr), "r"(parity) : "memory");
}
__device__ __forceinline__ void mbar_expect(uint32_t addr, uint32_t bytes) {
    asm volatile("mbarrier.arrive.expect_tx.shared.b64 _, [%0], %1;"
                 :: "r"(addr), "r"(bytes) : "memory");
}

__global__ void __cluster_dims__(2, 1, 1) __launch_bounds__(256, 1)
rnn_scan_kernel(const float* __restrict__ Whh, const float* __restrict__ bhh,
                float* __restrict__ out)
{
    __shared__ __align__(16) float h_sm[2][128];      // own outputs = our k-range
    __shared__ __align__(16) float recv_sm[2][128];   // peer partials (bulk dst)
    __shared__ __align__(16) float stage_sm[2][128];  // local partials (bulk src)
    __shared__ __align__(16) u64 mbar[2];             // one barrier per step parity

    const int tid = threadIdx.x;
    uint32_t rank;
    asm("mov.u32 %0, %%cluster_ctarank;" : "=r"(rank));
    const int  batch       = blockIdx.x >> 1;
    const int  jl          = tid & 127;
    const bool is_combine  = ((tid >> 7) == (int)rank);      // owns output j=tid
    const bool elected     = (tid == (int)(rank << 7));      // combiner leader
    const bool send_leader = (tid == (int)((rank ^ 1u) << 7)); // sender leader
    const int  kbase       = (int)rank * 128;

    // --- W_hh[tid][kbase .. kbase+127] -> 64 packed f32x2 registers ---
    u64 w2[64];
    {
        const ulonglong2* wrow = (const ulonglong2*)(Whh + (size_t)tid * 256 + kbase);
#pragma unroll
        for (int i = 0; i < 32; i++) {
            ulonglong2 v = wrow[i];
            w2[2 * i] = v.x; w2[2 * i + 1] = v.y;
        }
    }

    // --- init ---
    if (tid < 128) { h_sm[0][tid] = 0.0f; h_sm[1][tid] = 0.0f; }
    uint32_t mbar_a0 = smem_u32(&mbar[0]);
    uint32_t mbar_a1 = smem_u32(&mbar[1]);
    if (tid == 0) {
        asm volatile("mbarrier.init.shared.b64 [%0], 1;" :: "r"(mbar_a0) : "memory");
        asm volatile("mbarrier.init.shared.b64 [%0], 1;" :: "r"(mbar_a1) : "memory");
    }
    __syncthreads();
    if (elected) {              // pre-arm phases for t=0 and t=1
        mbar_expect(mbar_a0, 512u);
        mbar_expect(mbar_a1, 512u);
    }
    asm volatile("barrier.cluster.arrive.aligned;" ::: "memory");
    asm volatile("barrier.cluster.wait.aligned;" ::: "memory");

    uint32_t recv_a  = smem_u32(&recv_sm[0][0]);
    uint32_t stage_a = smem_u32(&stage_sm[0][0]);
    uint32_t peer = rank ^ 1u;
    uint32_t recv_peer, mbar_peer[2];
    asm("mapa.shared::cluster.u32 %0, %1, %2;" : "=r"(recv_peer)    : "r"(recv_a),  "r"(peer));
    asm("mapa.shared::cluster.u32 %0, %1, %2;" : "=r"(mbar_peer[0]) : "r"(mbar_a0), "r"(peer));
    asm("mapa.shared::cluster.u32 %0, %1, %2;" : "=r"(mbar_peer[1]) : "r"(mbar_a1), "r"(peer));

    float* outb = out + (size_t)batch * (1024 * 256) + tid;   // column j = tid
    const float bh = bhh[tid];
    float xp_next  = is_combine ? outb[0]   : 0.0f;   // xp(t)   two-deep prefetch
    float xp_next2 = is_combine ? outb[256] : 0.0f;   // xp(t+1)

    for (int t = 0; t < 1024; t++) {
        const int p = t & 1;

        // --- partial for output j=tid over k in J_r (h local, broadcast LDS) ---
        const ulonglong2* h4 = (const ulonglong2*)&h_sm[p][0];
        u64 acc0 = 0ull, acc1 = 0ull;
#pragma unroll
        for (int i = 0; i < 16; i++) {
            ulonglong2 va = h4[2 * i];
            acc0 = ffma2(w2[4 * i],     va.x, acc0);
            acc1 = ffma2(w2[4 * i + 1], va.y, acc1);
            ulonglong2 vb = h4[2 * i + 1];
            acc0 = ffma2(w2[4 * i + 2], vb.x, acc0);
            acc1 = ffma2(w2[4 * i + 3], vb.y, acc1);
        }
        float2 a0 = unpack2(acc0), a1 = unpack2(acc1);
        const float s = (a0.x + a0.y) + (a1.x + a1.y);

        if (!is_combine) {
            // stage partial locally (conflict-free STS.32)
            stage_sm[p][jl] = s;
            // all 4 sender warps done staging
            asm volatile("bar.sync 1, 128;" ::: "memory");
            if (send_leader) {
                // make generic-proxy STS visible to the async-proxy bulk read
                asm volatile("fence.proxy.async.shared::cta;" ::: "memory");
                // ONE 512B smem->peer-smem copy; ONE complete_tx at peer barrier
                asm volatile(
                    "cp.async.bulk.shared::cluster.shared::cta.mbarrier::complete_tx::bytes "
                    "[%0], [%1], %2, [%3];"
                    :: "r"(recv_peer + (uint32_t)(p << 9)),
                       "r"(stage_a  + (uint32_t)(p << 9)),
                       "r"(512u), "r"(mbar_peer[p]) : "memory");
            }
        } else {
            const float xp_cur = xp_next;
            xp_next = xp_next2;
            // barrier[p] flips once every 2 steps -> parity = (t>>1)&1
            mbar_wait_cluster(p ? mbar_a1 : mbar_a0, (uint32_t)((t >> 1) & 1));
            // re-arm THIS barrier for step t+2 (before syncthreads: race-free)
            if (elected && t < 1022)
                mbar_expect(p ? mbar_a1 : mbar_a0, 512u);
            const float tot = s + recv_sm[p][jl] + xp_cur + bh;
            const float h = tanh_acc(tot);
            h_sm[p ^ 1][jl] = h;                       // local h for next step
            outb[(size_t)t * 256] = h;                 // final output
            if (t < 1022) xp_next2 = __ldg(outb + (size_t)(t + 2) * 256);
        }
        __syncthreads();   // h_{t+1} visible to senders+combiners before next FMA
    }

    // keep smem alive until peer's in-flight bulk copies complete
    asm volatile("barrier.cluster.arrive.aligned;" ::: "memory");
    asm volatile("barrier.cluster.wait.aligned;" ::: "memory");
}

// ---------------------------------------------------------------------------
// Harness entry. Inputs: x, W_ih, W_hh, b_ih, b_hh. Output fp32 [B,T,H].
// x_proj is materialized into d_out, then overwritten in place by h_t.
// ---------------------------------------------------------------------------
extern "C" void kernel_launch(void* const* d_in, const int* in_sizes, int n_in,
                              void* d_out, int out_size)
{
    const float* x   = (const float*)d_in[0];
    const float* Wih = (const float*)d_in[1];
    const float* Whh = (const float*)d_in[2];
    const float* bih = (const float*)d_in[3];
    const float* bhh = (const float*)d_in[4];
    float* out = (float*)d_out;

    dim3 g1(2, 512);
    xproj_kernel<<<g1, 256>>>(x, Wih, bih, out);

    rnn_scan_kernel<<<128, 256>>>(Whh, bhh, out);
}

// round 8
// speedup vs baseline: 1.0005x; 1.0005x over previous
#include <cuda_runtime.h>
#include <cstdint>
#include <math.h>

typedef unsigned long long u64;

// ---------------------------------------------------------------------------
// Packed f32x2 helpers (Blackwell sm_103a)
// ---------------------------------------------------------------------------
__device__ __forceinline__ u64 ffma2(u64 a, u64 b, u64 c) {
    u64 d;
    asm("fma.rn.f32x2 %0, %1, %2, %3;" : "=l"(d) : "l"(a), "l"(b), "l"(c));
    return d;
}
__device__ __forceinline__ u64 pack2(float x, float y) {
    u64 r;
    asm("mov.b64 %0, {%1, %2};" : "=l"(r) : "f"(x), "f"(y));
    return r;
}
__device__ __forceinline__ float2 unpack2(u64 v) {
    float2 f;
    asm("mov.b64 {%0, %1}, %2;" : "=f"(f.x), "=f"(f.y) : "l"(v));
    return f;
}
__device__ __forceinline__ uint32_t smem_u32(const void* p) {
    uint32_t a;
    asm("{ .reg .u64 t; cvta.to.shared.u64 t, %1; cvt.u32.u64 %0, t; }"
        : "=r"(a) : "l"(p));
    return a;
}

// Accurate tanh via ex2.approx (rel err ~2^-22); tanhf under fast-math lowers
// to tanh.approx (abs err ~2^-11) and fails 1e-3 over 1024 recurrent steps.
__device__ __forceinline__ float tanh_acc(float x) {
    float e = __expf(2.0f * x);
    return 1.0f - 2.0f / (e + 1.0f);
}

// ---------------------------------------------------------------------------
// Phase 1: x_proj GEMM (unchanged; ~231us)
// ---------------------------------------------------------------------------
__global__ void __launch_bounds__(256) xproj_kernel(
    const float* __restrict__ X, const float* __restrict__ Wih,
    const float* __restrict__ bih, float* __restrict__ C)
{
    __shared__ __align__(16) float As[16][128];
    __shared__ __align__(16) float Bs[16][128];

    const int tid = threadIdx.x;
    const int tx  = tid & 15;
    const int ty  = tid >> 4;
    const int m0  = blockIdx.y * 128;
    const int n0  = blockIdx.x * 128;

    u64 acc[8][4];
#pragma unroll
    for (int m = 0; m < 8; m++)
#pragma unroll
        for (int n = 0; n < 4; n++) acc[m][n] = 0ull;

    for (int k0 = 0; k0 < 256; k0 += 16) {
#pragma unroll
        for (int i = 0; i < 2; i++) {
            int idx = tid + i * 256;
            int row = idx >> 2;
            int kq  = (idx & 3) << 2;
            float4 xa = *(const float4*)(X + (size_t)(m0 + row) * 256 + k0 + kq);
            As[kq + 0][row] = xa.x; As[kq + 1][row] = xa.y;
            As[kq + 2][row] = xa.z; As[kq + 3][row] = xa.w;
            float4 wa = *(const float4*)(Wih + (size_t)(n0 + row) * 256 + k0 + kq);
            Bs[kq + 0][row] = wa.x; Bs[kq + 1][row] = wa.y;
            Bs[kq + 2][row] = wa.z; Bs[kq + 3][row] = wa.w;
        }
        __syncthreads();

#pragma unroll
        for (int kk = 0; kk < 16; kk++) {
            float4 a0 = *(const float4*)&As[kk][ty * 8];
            float4 a1 = *(const float4*)&As[kk][ty * 8 + 4];
            float4 b0 = *(const float4*)&Bs[kk][tx * 8];
            float4 b1 = *(const float4*)&Bs[kk][tx * 8 + 4];
            u64 bb[4] = { pack2(b0.x, b0.y), pack2(b0.z, b0.w),
                          pack2(b1.x, b1.y), pack2(b1.z, b1.w) };
            float am[8] = { a0.x, a0.y, a0.z, a0.w, a1.x, a1.y, a1.z, a1.w };
#pragma unroll
            for (int m = 0; m < 8; m++) {
                u64 ad = pack2(am[m], am[m]);
#pragma unroll
                for (int n = 0; n < 4; n++) acc[m][n] = ffma2(ad, bb[n], acc[m][n]);
            }
        }
        __syncthreads();
    }

    const int nc = n0 + tx * 8;
    float4 bv0 = *(const float4*)(bih + nc);
    float4 bv1 = *(const float4*)(bih + nc + 4);
#pragma unroll
    for (int m = 0; m < 8; m++) {
        float2 r0 = unpack2(acc[m][0]), r1 = unpack2(acc[m][1]);
        float2 r2 = unpack2(acc[m][2]), r3 = unpack2(acc[m][3]);
        float* cp = C + (size_t)(m0 + ty * 8 + m) * 256 + nc;
        *(float4*)cp       = make_float4(r0.x + bv0.x, r0.y + bv0.y,
                                         r1.x + bv0.z, r1.y + bv0.w);
        *(float4*)(cp + 4) = make_float4(r2.x + bv1.x, r2.y + bv1.y,
                                         r3.x + bv1.z, r3.y + bv1.w);
    }
}

// ---------------------------------------------------------------------------
// Phase 2 (v8): R4 protocol + per-warp barriers + 2 batches per cluster.
// (R7 design with the barrier/recv ADDRESSING fixed — R7's aliased offsets
//  deadlocked; the protocol itself was never at fault.)
//
// Address scheme (single source of truth):
//   mbar[p][a][w]   (u64)   : mbar_base + (p<<6 | a<<5 | w<<3)
//   recv[p][a][jl]  (float) : recv_base + (p<<10 | a<<9 | jl<<2)
//
// Cluster of 2 CTAs serves TWO batch rows (same W_hh registers). CTA r owns
// outputs/k-range J_r; h never crosses the cluster. Sender warp wsub ships
// 8 st.async.v4 (=128B) to mbar[p][a][wsub], the barrier of the PAIRED
// combiner warp. 4 barriers per (p,a) drain in parallel; each combiner warp
// waits only its own. Batch 0 exchange hides under batch 1 FMA.
//
// Parity sets: mbar[p][..] serves steps t = p (mod 2); wait parity (t>>1)&1;
// re-arm for t+2 posted between wait(t) and __syncthreads(t). Chain (R4):
//   peer send(t+2) >= peer sync(t+1) >= peer wait(t+1) >= our send(t+1)
//   >= our sync(t) >= our expect(t+2).
// ---------------------------------------------------------------------------
__device__ __forceinline__ void mbar_wait_cluster(uint32_t addr, uint32_t parity) {
    asm volatile(
        "{\n\t"
        ".reg .pred P;\n\t"
        "LAB_W_%=:\n\t"
        "mbarrier.try_wait.parity.acquire.cluster.shared::cta.b64 P, [%0], %1, 0x989680;\n\t"
        "@P bra.uni LAB_D_%=;\n\t"
        "bra.uni LAB_W_%=;\n\t"
        "LAB_D_%=:\n\t"
        "}"
        :: "r"(addr), "r"(parity) : "memory");
}
__device__ __forceinline__ void mbar_expect(uint32_t addr, uint32_t bytes) {
    asm volatile("mbarrier.arrive.expect_tx.shared.b64 _, [%0], %1;"
                 :: "r"(addr), "r"(bytes) : "memory");
}
__device__ __forceinline__ void send_v4(uint32_t raddr, float s, float s1,
                                        float s2, float s3, uint32_t mbar) {
    asm volatile(
        "st.async.shared::cluster.mbarrier::complete_tx::bytes.v4.b32 "
        "[%0], {%1, %2, %3, %4}, [%5];"
        :: "r"(raddr),
           "r"(__float_as_uint(s)),  "r"(__float_as_uint(s1)),
           "r"(__float_as_uint(s2)), "r"(__float_as_uint(s3)),
           "r"(mbar) : "memory");
}

__global__ void __cluster_dims__(2, 1, 1) __launch_bounds__(256, 1)
rnn_scan_kernel(const float* __restrict__ Whh, const float* __restrict__ bhh,
                float* __restrict__ out)
{
    __shared__ __align__(16) float h_sm[2][2][128];     // [batch][parity][jl]
    __shared__ __align__(16) float recv_sm[2][2][128];  // [parity][batch][jl]
    __shared__ __align__(16) u64 mbar[2][2][4];         // [parity][batch][warp]

    const int tid = threadIdx.x;
    uint32_t rank;
    asm("mov.u32 %0, %%cluster_ctarank;" : "=r"(rank));
    const int  cid        = blockIdx.x >> 1;             // cluster id: 2 batches
    const int  jl         = tid & 127;
    const uint32_t wsub   = (uint32_t)((tid >> 5) & 3);  // warp index in role group
    const bool is_combine = ((tid >> 7) == (int)rank);   // owns output j=tid
    const int  kbase      = (int)rank * 128;

    // --- W_hh[tid][kbase .. kbase+127] -> 64 packed f32x2 regs (shared by
    //     both batches) ---
    u64 w2[64];
    {
        const ulonglong2* wrow = (const ulonglong2*)(Whh + (size_t)tid * 256 + kbase);
#pragma unroll
        for (int i = 0; i < 32; i++) {
            ulonglong2 v = wrow[i];
            w2[2 * i] = v.x; w2[2 * i + 1] = v.y;
        }
    }

    // --- init ---
    if (tid < 128) {
        h_sm[0][0][tid] = 0.0f; h_sm[0][1][tid] = 0.0f;
        h_sm[1][0][tid] = 0.0f; h_sm[1][1][tid] = 0.0f;
    }
    uint32_t mbar_base = smem_u32(&mbar[0][0][0]);
    if (tid < 16)   // 16 barriers [p][a][w], arrive count 1 (the arming lane)
        asm volatile("mbarrier.init.shared.b64 [%0], 1;"
                     :: "r"(mbar_base + (uint32_t)tid * 8u) : "memory");
    __syncthreads();
    // pre-arm all 4 (p,a) uses of this combiner warp's barrier (128B each)
    if (is_combine && (tid & 31) == 0) {
#pragma unroll
        for (uint32_t pa = 0; pa < 4; pa++)   // pa = p*2 + a
            mbar_expect(mbar_base + ((pa << 5) | (wsub << 3)), 128u);
    }
    asm volatile("barrier.cluster.arrive.aligned;" ::: "memory");
    asm volatile("barrier.cluster.wait.aligned;" ::: "memory");

    uint32_t recv_a = smem_u32(&recv_sm[0][0][0]);
    uint32_t peer = rank ^ 1u;
    uint32_t recv_peer, mbar_peer_base;
    asm("mapa.shared::cluster.u32 %0, %1, %2;" : "=r"(recv_peer)      : "r"(recv_a),    "r"(peer));
    asm("mapa.shared::cluster.u32 %0, %1, %2;" : "=r"(mbar_peer_base) : "r"(mbar_base), "r"(peer));

    float* outb0 = out + (size_t)(cid * 2 + 0) * (1024 * 256) + tid;  // column j
    float* outb1 = out + (size_t)(cid * 2 + 1) * (1024 * 256) + tid;
    const float bh = bhh[tid];
    float xp0 = is_combine ? outb0[0] : 0.0f;
    float xp1 = is_combine ? outb1[0] : 0.0f;

    for (int t = 0; t < 1024; t++) {
        const uint32_t p = (uint32_t)(t & 1);

        // ---- batch 0 partial (h local, broadcast LDS) ----
        const ulonglong2* h4a = (const ulonglong2*)&h_sm[0][p][0];
        u64 a0 = 0ull, a1 = 0ull;
#pragma unroll
        for (int i = 0; i < 16; i++) {
            ulonglong2 va = h4a[2 * i];
            a0 = ffma2(w2[4 * i],     va.x, a0);
            a1 = ffma2(w2[4 * i + 1], va.y, a1);
            ulonglong2 vb = h4a[2 * i + 1];
            a0 = ffma2(w2[4 * i + 2], vb.x, a0);
            a1 = ffma2(w2[4 * i + 3], vb.y, a1);
        }
        float2 f0 = unpack2(a0), f1 = unpack2(a1);
        const float s0 = (f0.x + f0.y) + (f1.x + f1.y);

        if (!is_combine) {   // ship batch-0 partials while batch-1 FMA runs
            const float u1 = __shfl_down_sync(0xFFFFFFFFu, s0, 1);
            const float u2 = __shfl_down_sync(0xFFFFFFFFu, s0, 2);
            const float u3 = __shfl_down_sync(0xFFFFFFFFu, s0, 3);
            if ((tid & 3) == 0)
                send_v4(recv_peer + ((p << 10) | ((uint32_t)jl << 2)),   // [p][0][jl]
                        s0, u1, u2, u3,
                        mbar_peer_base + ((p << 6) | (wsub << 3)));      // [p][0][w]
        }

        // ---- batch 1 partial ----
        const ulonglong2* h4b = (const ulonglong2*)&h_sm[1][p][0];
        u64 b0 = 0ull, b1 = 0ull;
#pragma unroll
        for (int i = 0; i < 16; i++) {
            ulonglong2 va = h4b[2 * i];
            b0 = ffma2(w2[4 * i],     va.x, b0);
            b1 = ffma2(w2[4 * i + 1], va.y, b1);
            ulonglong2 vb = h4b[2 * i + 1];
            b0 = ffma2(w2[4 * i + 2], vb.x, b0);
            b1 = ffma2(w2[4 * i + 3], vb.y, b1);
        }
        float2 g0 = unpack2(b0), g1 = unpack2(b1);
        const float s1b = (g0.x + g0.y) + (g1.x + g1.y);

        if (!is_combine) {
            const float u1 = __shfl_down_sync(0xFFFFFFFFu, s1b, 1);
            const float u2 = __shfl_down_sync(0xFFFFFFFFu, s1b, 2);
            const float u3 = __shfl_down_sync(0xFFFFFFFFu, s1b, 3);
            if ((tid & 3) == 0)
                send_v4(recv_peer + ((p << 10) | (1u << 9) | ((uint32_t)jl << 2)), // [p][1][jl]
                        s1b, u1, u2, u3,
                        mbar_peer_base + ((p << 6) | (1u << 5) | (wsub << 3)));    // [p][1][w]
        } else {
            const uint32_t wpar = (uint32_t)((t >> 1) & 1);
            // ---- combine batch 0 (transit hid under batch-1 FMA) ----
            const uint32_t mb0 = mbar_base + ((p << 6) | (wsub << 3));   // [p][0][w]
            mbar_wait_cluster(mb0, wpar);
            if ((tid & 31) == 0 && t < 1022) mbar_expect(mb0, 128u);
            const float h0 = tanh_acc(s0 + recv_sm[p][0][jl] + xp0 + bh);
            h_sm[0][p ^ 1][jl] = h0;
            outb0[(size_t)t * 256] = h0;
            if (t < 1023) xp0 = __ldg(outb0 + (size_t)(t + 1) * 256);
            // ---- combine batch 1 ----
            const uint32_t mb1 = mb0 + 32u;                              // [p][1][w]
            mbar_wait_cluster(mb1, wpar);
            if ((tid & 31) == 0 && t < 1022) mbar_expect(mb1, 128u);
            const float h1 = tanh_acc(s1b + recv_sm[p][1][jl] + xp1 + bh);
            h_sm[1][p ^ 1][jl] = h1;
            outb1[(size_t)t * 256] = h1;
            if (t < 1023) xp1 = __ldg(outb1 + (size_t)(t + 1) * 256);
        }
        __syncthreads();   // h_{t+1} (both batches) visible before next FMA
    }

    // keep smem alive until peer's in-flight st.async complete
    asm volatile("barrier.cluster.arrive.aligned;" ::: "memory");
    asm volatile("barrier.cluster.wait.aligned;" ::: "memory");
}

// ---------------------------------------------------------------------------
// Harness entry. Inputs: x, W_ih, W_hh, b_ih, b_hh. Output fp32 [B,T,H].
// x_proj is materialized into d_out, then overwritten in place by h_t.
// ---------------------------------------------------------------------------
extern "C" void kernel_launch(void* const* d_in, const int* in_sizes, int n_in,
                              void* d_out, int out_size)
{
    const float* x   = (const float*)d_in[0];
    const float* Wih = (const float*)d_in[1];
    const float* Whh = (const float*)d_in[2];
    const float* bih = (const float*)d_in[3];
    const float* bhh = (const float*)d_in[4];
    float* out = (float*)d_out;

    dim3 g1(2, 512);
    xproj_kernel<<<g1, 256>>>(x, Wih, bih, out);

    // 32 clusters x 2 CTAs, 2 batches per cluster
    rnn_scan_kernel<<<64, 256>>>(Whh, bhh, out);
}

// round 9
// speedup vs baseline: 1.1241x; 1.1235x over previous
#include <cuda_runtime.h>
#include <cstdint>
#include <math.h>

typedef unsigned long long u64;

// ---------------------------------------------------------------------------
// Packed f32x2 helpers (Blackwell sm_103a)
// ---------------------------------------------------------------------------
__device__ __forceinline__ u64 ffma2(u64 a, u64 b, u64 c) {
    u64 d;
    asm("fma.rn.f32x2 %0, %1, %2, %3;" : "=l"(d) : "l"(a), "l"(b), "l"(c));
    return d;
}
__device__ __forceinline__ u64 pack2(float x, float y) {
    u64 r;
    asm("mov.b64 %0, {%1, %2};" : "=l"(r) : "f"(x), "f"(y));
    return r;
}
__device__ __forceinline__ float2 unpack2(u64 v) {
    float2 f;
    asm("mov.b64 {%0, %1}, %2;" : "=f"(f.x), "=f"(f.y) : "l"(v));
    return f;
}
__device__ __forceinline__ uint32_t smem_u32(const void* p) {
    uint32_t a;
    asm("{ .reg .u64 t; cvta.to.shared.u64 t, %1; cvt.u32.u64 %0, t; }"
        : "=r"(a) : "l"(p));
    return a;
}

// Accurate tanh via ex2.approx (rel err ~2^-22); tanhf under fast-math lowers
// to tanh.approx (abs err ~2^-11) and fails 1e-3 over 1024 recurrent steps.
__device__ __forceinline__ float tanh_acc(float x) {
    float e = __expf(2.0f * x);
    return 1.0f - 2.0f / (e + 1.0f);
}

// ---------------------------------------------------------------------------
// Phase 1: x_proj GEMM (unchanged; ~231us)
// ---------------------------------------------------------------------------
__global__ void __launch_bounds__(256) xproj_kernel(
    const float* __restrict__ X, const float* __restrict__ Wih,
    const float* __restrict__ bih, float* __restrict__ C)
{
    __shared__ __align__(16) float As[16][128];
    __shared__ __align__(16) float Bs[16][128];

    const int tid = threadIdx.x;
    const int tx  = tid & 15;
    const int ty  = tid >> 4;
    const int m0  = blockIdx.y * 128;
    const int n0  = blockIdx.x * 128;

    u64 acc[8][4];
#pragma unroll
    for (int m = 0; m < 8; m++)
#pragma unroll
        for (int n = 0; n < 4; n++) acc[m][n] = 0ull;

    for (int k0 = 0; k0 < 256; k0 += 16) {
#pragma unroll
        for (int i = 0; i < 2; i++) {
            int idx = tid + i * 256;
            int row = idx >> 2;
            int kq  = (idx & 3) << 2;
            float4 xa = *(const float4*)(X + (size_t)(m0 + row) * 256 + k0 + kq);
            As[kq + 0][row] = xa.x; As[kq + 1][row] = xa.y;
            As[kq + 2][row] = xa.z; As[kq + 3][row] = xa.w;
            float4 wa = *(const float4*)(Wih + (size_t)(n0 + row) * 256 + k0 + kq);
            Bs[kq + 0][row] = wa.x; Bs[kq + 1][row] = wa.y;
            Bs[kq + 2][row] = wa.z; Bs[kq + 3][row] = wa.w;
        }
        __syncthreads();

#pragma unroll
        for (int kk = 0; kk < 16; kk++) {
            float4 a0 = *(const float4*)&As[kk][ty * 8];
            float4 a1 = *(const float4*)&As[kk][ty * 8 + 4];
            float4 b0 = *(const float4*)&Bs[kk][tx * 8];
            float4 b1 = *(const float4*)&Bs[kk][tx * 8 + 4];
            u64 bb[4] = { pack2(b0.x, b0.y), pack2(b0.z, b0.w),
                          pack2(b1.x, b1.y), pack2(b1.z, b1.w) };
            float am[8] = { a0.x, a0.y, a0.z, a0.w, a1.x, a1.y, a1.z, a1.w };
#pragma unroll
            for (int m = 0; m < 8; m++) {
                u64 ad = pack2(am[m], am[m]);
#pragma unroll
                for (int n = 0; n < 4; n++) acc[m][n] = ffma2(ad, bb[n], acc[m][n]);
            }
        }
        __syncthreads();
    }

    const int nc = n0 + tx * 8;
    float4 bv0 = *(const float4*)(bih + nc);
    float4 bv1 = *(const float4*)(bih + nc + 4);
#pragma unroll
    for (int m = 0; m < 8; m++) {
        float2 r0 = unpack2(acc[m][0]), r1 = unpack2(acc[m][1]);
        float2 r2 = unpack2(acc[m][2]), r3 = unpack2(acc[m][3]);
        float* cp = C + (size_t)(m0 + ty * 8 + m) * 256 + nc;
        *(float4*)cp       = make_float4(r0.x + bv0.x, r0.y + bv0.y,
                                         r1.x + bv0.z, r1.y + bv0.w);
        *(float4*)(cp + 4) = make_float4(r2.x + bv1.x, r2.y + bv1.y,
                                         r3.x + bv1.z, r3.y + bv1.w);
    }
}

// ---------------------------------------------------------------------------
// Phase 2 (v9): R4 structure, mbarrier-FREE signaling via release/acquire
// flag polling.
//
// Cluster of 2 CTAs per batch (64 clusters); CTA r owns outputs/k-range J_r;
// h never crosses the cluster; W_hh fully register-resident (64 u64/thread).
//
// Per step: sender lane jl stores its partial with ONE weak
// st.shared::cluster.b32 into peer recv[p][jl] (32 parallel stores/warp,
// distinct addresses -> no SYNCS serialization, no shfl packing). Then
// __syncwarp, and lane0 st.release.cluster's a MONOTONIC counter (t+1) into
// the paired combiner warp's flag word. Combiner warp spin-polls its own
// flag with ld.acquire.cluster (broadcast LDS) until >= t+1, then reads the
// data. No mbarrier: no arrive-drain, no expect_tx re-arm, no TRYWAIT wake,
// and the monotonic counter makes underflow races structurally impossible.
//
// WAR safety on recv/h parity buffers (R4 chain, now via rel/acq flags):
//   our read recv(t) -> our sync(t) -> our send+flag(t+1) -> (rel/acq) ->
//   peer wait(t+1) -> peer sync(t+1) -> peer writes recv(t+2).
// ---------------------------------------------------------------------------
__global__ void __cluster_dims__(2, 1, 1) __launch_bounds__(256, 1)
rnn_scan_kernel(const float* __restrict__ Whh, const float* __restrict__ bhh,
                float* __restrict__ out)
{
    __shared__ __align__(16) float h_sm[2][128];      // own outputs = our k-range
    __shared__ __align__(16) float recv_sm[2][128];   // peer partials [parity][jl]
    __shared__ __align__(16) uint32_t flag_sm[2][4];  // [parity][warp] counters

    const int tid = threadIdx.x;
    uint32_t rank;
    asm("mov.u32 %0, %%cluster_ctarank;" : "=r"(rank));
    const int      batch      = blockIdx.x >> 1;
    const int      jl         = tid & 127;
    const uint32_t wsub       = (uint32_t)((tid >> 5) & 3);  // warp in role group
    const bool     is_combine = ((tid >> 7) == (int)rank);   // owns output j=tid
    const int      kbase      = (int)rank * 128;

    // --- W_hh[tid][kbase .. kbase+127] -> 64 packed f32x2 registers ---
    u64 w2[64];
    {
        const ulonglong2* wrow = (const ulonglong2*)(Whh + (size_t)tid * 256 + kbase);
#pragma unroll
        for (int i = 0; i < 32; i++) {
            ulonglong2 v = wrow[i];
            w2[2 * i] = v.x; w2[2 * i + 1] = v.y;
        }
    }

    // --- init ---
    if (tid < 128) { h_sm[0][tid] = 0.0f; h_sm[1][tid] = 0.0f; }
    if (tid < 8) flag_sm[tid >> 2][tid & 3] = 0u;
    __syncthreads();
    asm volatile("barrier.cluster.arrive.aligned;" ::: "memory");
    asm volatile("barrier.cluster.wait.aligned;" ::: "memory");

    uint32_t recv_a = smem_u32(&recv_sm[0][0]);
    uint32_t flag_a = smem_u32(&flag_sm[0][0]);
    uint32_t peer = rank ^ 1u;
    uint32_t recv_peer, flag_peer;
    asm("mapa.shared::cluster.u32 %0, %1, %2;" : "=r"(recv_peer) : "r"(recv_a), "r"(peer));
    asm("mapa.shared::cluster.u32 %0, %1, %2;" : "=r"(flag_peer) : "r"(flag_a), "r"(peer));

    float* outb = out + (size_t)batch * (1024 * 256) + tid;   // column j = tid
    const float bh = bhh[tid];
    float xp_next = is_combine ? outb[0] : 0.0f;

    for (int t = 0; t < 1024; t++) {
        const uint32_t p = (uint32_t)(t & 1);

        // --- partial for output j=tid over k in J_r (h local, broadcast LDS) ---
        const ulonglong2* h4 = (const ulonglong2*)&h_sm[p][0];
        u64 acc0 = 0ull, acc1 = 0ull;
#pragma unroll
        for (int i = 0; i < 16; i++) {
            ulonglong2 va = h4[2 * i];
            acc0 = ffma2(w2[4 * i],     va.x, acc0);
            acc1 = ffma2(w2[4 * i + 1], va.y, acc1);
            ulonglong2 vb = h4[2 * i + 1];
            acc0 = ffma2(w2[4 * i + 2], vb.x, acc0);
            acc1 = ffma2(w2[4 * i + 3], vb.y, acc1);
        }
        float2 a0 = unpack2(acc0), a1 = unpack2(acc1);
        const float s = (a0.x + a0.y) + (a1.x + a1.y);

        if (!is_combine) {
            // one weak DSMEM store per lane (32 parallel, distinct addresses)
            asm volatile("st.shared::cluster.b32 [%0], %1;"
                         :: "r"(recv_peer + ((p << 9) | ((uint32_t)jl << 2))),
                            "r"(__float_as_uint(s)) : "memory");
            __syncwarp();
            // lane0 publishes: release-store of monotonic counter t+1
            if ((tid & 31) == 0)
                asm volatile("st.release.cluster.shared::cluster.b32 [%0], %1;"
                             :: "r"(flag_peer + ((p << 4) | (wsub << 2))),
                                "r"((uint32_t)(t + 1)) : "memory");
        } else {
            const float xp_cur = xp_next;
            // spin-poll own flag (broadcast LDS, acquire at cluster scope)
            {
                const uint32_t fa = flag_a + ((p << 4) | (wsub << 2));
                uint32_t v;
                do {
                    asm volatile("ld.acquire.cluster.shared::cta.b32 %0, [%1];"
                                 : "=r"(v) : "r"(fa) : "memory");
                } while ((int)v < t + 1);
            }
            const float tot = s + recv_sm[p][jl] + xp_cur + bh;
            const float h = tanh_acc(tot);
            h_sm[p ^ 1][jl] = h;                       // local h for next step
            outb[(size_t)t * 256] = h;                 // final output
            if (t < 1023) xp_next = __ldg(outb + (size_t)(t + 1) * 256);
        }
        __syncthreads();   // h_{t+1} visible to all before next FMA
    }

    // keep smem alive until peer's in-flight remote stores complete
    asm volatile("barrier.cluster.arrive.aligned;" ::: "memory");
    asm volatile("barrier.cluster.wait.aligned;" ::: "memory");
}

// ---------------------------------------------------------------------------
// Harness entry. Inputs: x, W_ih, W_hh, b_ih, b_hh. Output fp32 [B,T,H].
// x_proj is materialized into d_out, then overwritten in place by h_t.
// ---------------------------------------------------------------------------
extern "C" void kernel_launch(void* const* d_in, const int* in_sizes, int n_in,
                              void* d_out, int out_size)
{
    const float* x   = (const float*)d_in[0];
    const float* Wih = (const float*)d_in[1];
    const float* Whh = (const float*)d_in[2];
    const float* bih = (const float*)d_in[3];
    const float* bhh = (const float*)d_in[4];
    float* out = (float*)d_out;

    dim3 g1(2, 512);
    xproj_kernel<<<g1, 256>>>(x, Wih, bih, out);

    // 64 clusters x 2 CTAs, 1 batch per cluster
    rnn_scan_kernel<<<128, 256>>>(Whh, bhh, out);
}

// round 10
// speedup vs baseline: 1.2154x; 1.0812x over previous
#include <cuda_runtime.h>
#include <cstdint>
#include <math.h>

typedef unsigned long long u64;

// ---------------------------------------------------------------------------
// Packed f32x2 helpers (Blackwell sm_103a)
// ---------------------------------------------------------------------------
__device__ __forceinline__ u64 ffma2(u64 a, u64 b, u64 c) {
    u64 d;
    asm("fma.rn.f32x2 %0, %1, %2, %3;" : "=l"(d) : "l"(a), "l"(b), "l"(c));
    return d;
}
__device__ __forceinline__ u64 pack2(float x, float y) {
    u64 r;
    asm("mov.b64 %0, {%1, %2};" : "=l"(r) : "f"(x), "f"(y));
    return r;
}
__device__ __forceinline__ float2 unpack2(u64 v) {
    float2 f;
    asm("mov.b64 {%0, %1}, %2;" : "=f"(f.x), "=f"(f.y) : "l"(v));
    return f;
}
__device__ __forceinline__ uint32_t smem_u32(const void* p) {
    uint32_t a;
    asm("{ .reg .u64 t; cvta.to.shared.u64 t, %1; cvt.u32.u64 %0, t; }"
        : "=r"(a) : "l"(p));
    return a;
}

// Accurate tanh via ex2.approx (rel err ~2^-22); tanhf under fast-math lowers
// to tanh.approx (abs err ~2^-11) and fails 1e-3 over 1024 recurrent steps.
__device__ __forceinline__ float tanh_acc(float x) {
    float e = __expf(2.0f * x);
    return 1.0f - 2.0f / (e + 1.0f);
}

// ---------------------------------------------------------------------------
// Phase 1: x_proj GEMM (unchanged; ~231us)
// ---------------------------------------------------------------------------
__global__ void __launch_bounds__(256) xproj_kernel(
    const float* __restrict__ X, const float* __restrict__ Wih,
    const float* __restrict__ bih, float* __restrict__ C)
{
    __shared__ __align__(16) float As[16][128];
    __shared__ __align__(16) float Bs[16][128];

    const int tid = threadIdx.x;
    const int tx  = tid & 15;
    const int ty  = tid >> 4;
    const int m0  = blockIdx.y * 128;
    const int n0  = blockIdx.x * 128;

    u64 acc[8][4];
#pragma unroll
    for (int m = 0; m < 8; m++)
#pragma unroll
        for (int n = 0; n < 4; n++) acc[m][n] = 0ull;

    for (int k0 = 0; k0 < 256; k0 += 16) {
#pragma unroll
        for (int i = 0; i < 2; i++) {
            int idx = tid + i * 256;
            int row = idx >> 2;
            int kq  = (idx & 3) << 2;
            float4 xa = *(const float4*)(X + (size_t)(m0 + row) * 256 + k0 + kq);
            As[kq + 0][row] = xa.x; As[kq + 1][row] = xa.y;
            As[kq + 2][row] = xa.z; As[kq + 3][row] = xa.w;
            float4 wa = *(const float4*)(Wih + (size_t)(n0 + row) * 256 + k0 + kq);
            Bs[kq + 0][row] = wa.x; Bs[kq + 1][row] = wa.y;
            Bs[kq + 2][row] = wa.z; Bs[kq + 3][row] = wa.w;
        }
        __syncthreads();

#pragma unroll
        for (int kk = 0; kk < 16; kk++) {
            float4 a0 = *(const float4*)&As[kk][ty * 8];
            float4 a1 = *(const float4*)&As[kk][ty * 8 + 4];
            float4 b0 = *(const float4*)&Bs[kk][tx * 8];
            float4 b1 = *(const float4*)&Bs[kk][tx * 8 + 4];
            u64 bb[4] = { pack2(b0.x, b0.y), pack2(b0.z, b0.w),
                          pack2(b1.x, b1.y), pack2(b1.z, b1.w) };
            float am[8] = { a0.x, a0.y, a0.z, a0.w, a1.x, a1.y, a1.z, a1.w };
#pragma unroll
            for (int m = 0; m < 8; m++) {
                u64 ad = pack2(am[m], am[m]);
#pragma unroll
                for (int n = 0; n < 4; n++) acc[m][n] = ffma2(ad, bb[n], acc[m][n]);
            }
        }
        __syncthreads();
    }

    const int nc = n0 + tx * 8;
    float4 bv0 = *(const float4*)(bih + nc);
    float4 bv1 = *(const float4*)(bih + nc + 4);
#pragma unroll
    for (int m = 0; m < 8; m++) {
        float2 r0 = unpack2(acc[m][0]), r1 = unpack2(acc[m][1]);
        float2 r2 = unpack2(acc[m][2]), r3 = unpack2(acc[m][3]);
        float* cp = C + (size_t)(m0 + ty * 8 + m) * 256 + nc;
        *(float4*)cp       = make_float4(r0.x + bv0.x, r0.y + bv0.y,
                                         r1.x + bv0.z, r1.y + bv0.w);
        *(float4*)(cp + 4) = make_float4(r2.x + bv1.x, r2.y + bv1.y,
                                         r3.x + bv1.z, r3.y + bv1.w);
    }
}

// ---------------------------------------------------------------------------
// Phase 2 (v10): R4 protocol + per-warp paired barriers, FULL grid.
// (= R8's verified design with the second batch removed: 64 clusters,
//  128 CTAs, 1 batch per cluster.)
//
// Address scheme:
//   mbar[p][w]   (u64)   : mbar_base + (p<<5 | w<<3)
//   recv[p][jl]  (float) : recv_base + (p<<9 | jl<<2)
//
// Cluster of 2 CTAs per batch. CTA r owns outputs/k-range J_r; h never
// crosses the cluster; W_hh fully register-resident. Sender warp wsub ships
// 8 st.async.v4 (=128B) to peer mbar[p][wsub] — the barrier of the PAIRED
// combiner warp (same wsub, same jl range). 4 barriers drain in parallel
// (8 tx-updates each, vs 32 on one address in R4); each combiner warp
// TRYWAITs only its own barrier. xp prefetch moved before the wait.
//
// Parity sets: mbar[p][..] serves steps t = p (mod 2); wait parity (t>>1)&1;
// re-arm for t+2 posted between wait(t) and __syncthreads(t). Chain (R4):
//   peer send(t+2) >= peer sync(t+1) >= peer wait(t+1) >= our send(t+1)
//   >= our sync(t) >= our expect(t+2).
// ---------------------------------------------------------------------------
__device__ __forceinline__ void mbar_wait_cluster(uint32_t addr, uint32_t parity) {
    asm volatile(
        "{\n\t"
        ".reg .pred P;\n\t"
        "LAB_W_%=:\n\t"
        "mbarrier.try_wait.parity.acquire.cluster.shared::cta.b64 P, [%0], %1, 0x989680;\n\t"
        "@P bra.uni LAB_D_%=;\n\t"
        "bra.uni LAB_W_%=;\n\t"
        "LAB_D_%=:\n\t"
        "}"
        :: "r"(addr), "r"(parity) : "memory");
}
__device__ __forceinline__ void mbar_expect(uint32_t addr, uint32_t bytes) {
    asm volatile("mbarrier.arrive.expect_tx.shared.b64 _, [%0], %1;"
                 :: "r"(addr), "r"(bytes) : "memory");
}
__device__ __forceinline__ void send_v4(uint32_t raddr, float s, float s1,
                                        float s2, float s3, uint32_t mbar) {
    asm volatile(
        "st.async.shared::cluster.mbarrier::complete_tx::bytes.v4.b32 "
        "[%0], {%1, %2, %3, %4}, [%5];"
        :: "r"(raddr),
           "r"(__float_as_uint(s)),  "r"(__float_as_uint(s1)),
           "r"(__float_as_uint(s2)), "r"(__float_as_uint(s3)),
           "r"(mbar) : "memory");
}

__global__ void __cluster_dims__(2, 1, 1) __launch_bounds__(256, 1)
rnn_scan_kernel(const float* __restrict__ Whh, const float* __restrict__ bhh,
                float* __restrict__ out)
{
    __shared__ __align__(16) float h_sm[2][128];     // own outputs = our k-range
    __shared__ __align__(16) float recv_sm[2][128];  // peer partials [parity][jl]
    __shared__ __align__(16) u64 mbar[2][4];         // [parity][warp]

    const int tid = threadIdx.x;
    uint32_t rank;
    asm("mov.u32 %0, %%cluster_ctarank;" : "=r"(rank));
    const int      batch      = blockIdx.x >> 1;
    const int      jl         = tid & 127;
    const uint32_t wsub       = (uint32_t)((tid >> 5) & 3);  // warp in role group
    const bool     is_combine = ((tid >> 7) == (int)rank);   // owns output j=tid
    const int      kbase      = (int)rank * 128;

    // --- W_hh[tid][kbase .. kbase+127] -> 64 packed f32x2 registers ---
    u64 w2[64];
    {
        const ulonglong2* wrow = (const ulonglong2*)(Whh + (size_t)tid * 256 + kbase);
#pragma unroll
        for (int i = 0; i < 32; i++) {
            ulonglong2 v = wrow[i];
            w2[2 * i] = v.x; w2[2 * i + 1] = v.y;
        }
    }

    // --- init ---
    if (tid < 128) { h_sm[0][tid] = 0.0f; h_sm[1][tid] = 0.0f; }
    uint32_t mbar_base = smem_u32(&mbar[0][0]);
    if (tid < 8)    // 8 barriers [p][w], arrive count 1 (the arming lane)
        asm volatile("mbarrier.init.shared.b64 [%0], 1;"
                     :: "r"(mbar_base + (uint32_t)tid * 8u) : "memory");
    __syncthreads();
    // pre-arm both parities of this combiner warp's barrier (128B each)
    if (is_combine && (tid & 31) == 0) {
        mbar_expect(mbar_base + ((0u << 5) | (wsub << 3)), 128u);
        mbar_expect(mbar_base + ((1u << 5) | (wsub << 3)), 128u);
    }
    asm volatile("barrier.cluster.arrive.aligned;" ::: "memory");
    asm volatile("barrier.cluster.wait.aligned;" ::: "memory");

    uint32_t recv_a = smem_u32(&recv_sm[0][0]);
    uint32_t peer = rank ^ 1u;
    uint32_t recv_peer, mbar_peer_base;
    asm("mapa.shared::cluster.u32 %0, %1, %2;" : "=r"(recv_peer)      : "r"(recv_a),    "r"(peer));
    asm("mapa.shared::cluster.u32 %0, %1, %2;" : "=r"(mbar_peer_base) : "r"(mbar_base), "r"(peer));

    float* outb = out + (size_t)batch * (1024 * 256) + tid;   // column j = tid
    const float bh = bhh[tid];
    float xp_next = is_combine ? outb[0] : 0.0f;

    for (int t = 0; t < 1024; t++) {
        const uint32_t p = (uint32_t)(t & 1);

        // --- partial for output j=tid over k in J_r (h local, broadcast LDS) ---
        const ulonglong2* h4 = (const ulonglong2*)&h_sm[p][0];
        u64 acc0 = 0ull, acc1 = 0ull;
#pragma unroll
        for (int i = 0; i < 16; i++) {
            ulonglong2 va = h4[2 * i];
            acc0 = ffma2(w2[4 * i],     va.x, acc0);
            acc1 = ffma2(w2[4 * i + 1], va.y, acc1);
            ulonglong2 vb = h4[2 * i + 1];
            acc0 = ffma2(w2[4 * i + 2], vb.x, acc0);
            acc1 = ffma2(w2[4 * i + 3], vb.y, acc1);
        }
        float2 a0 = unpack2(acc0), a1 = unpack2(acc1);
        const float s = (a0.x + a0.y) + (a1.x + a1.y);

        if (!is_combine) {
            // pack 4 partials/lane; 8 v4 st.async per warp -> paired barrier
            const float u1 = __shfl_down_sync(0xFFFFFFFFu, s, 1);
            const float u2 = __shfl_down_sync(0xFFFFFFFFu, s, 2);
            const float u3 = __shfl_down_sync(0xFFFFFFFFu, s, 3);
            if ((tid & 3) == 0)
                send_v4(recv_peer + ((p << 9) | ((uint32_t)jl << 2)),    // [p][jl]
                        s, u1, u2, u3,
                        mbar_peer_base + ((p << 5) | (wsub << 3)));      // [p][w]
        } else {
            const float xp_cur = xp_next;
            // prefetch next xp BEFORE blocking on the barrier
            if (t < 1023) xp_next = __ldg(outb + (size_t)(t + 1) * 256);
            // barrier[p] flips every 2 steps -> parity (t>>1)&1
            const uint32_t mb = mbar_base + ((p << 5) | (wsub << 3));
            mbar_wait_cluster(mb, (uint32_t)((t >> 1) & 1));
            // re-arm THIS barrier for t+2 (before syncthreads: race-free)
            if ((tid & 31) == 0 && t < 1022) mbar_expect(mb, 128u);
            const float tot = s + recv_sm[p][jl] + xp_cur + bh;
            const float h = tanh_acc(tot);
            h_sm[p ^ 1][jl] = h;                       // local h for next step
            outb[(size_t)t * 256] = h;                 // final output
        }
        __syncthreads();   // h_{t+1} visible to all before next FMA
    }

    // keep smem alive until peer's in-flight st.async complete
    asm volatile("barrier.cluster.arrive.aligned;" ::: "memory");
    asm volatile("barrier.cluster.wait.aligned;" ::: "memory");
}

// ---------------------------------------------------------------------------
// Harness entry. Inputs: x, W_ih, W_hh, b_ih, b_hh. Output fp32 [B,T,H].
// x_proj is materialized into d_out, then overwritten in place by h_t.
// ---------------------------------------------------------------------------
extern "C" void kernel_launch(void* const* d_in, const int* in_sizes, int n_in,
                              void* d_out, int out_size)
{
    const float* x   = (const float*)d_in[0];
    const float* Wih = (const float*)d_in[1];
    const float* Whh = (const float*)d_in[2];
    const float* bih = (const float*)d_in[3];
    const float* bhh = (const float*)d_in[4];
    float* out = (float*)d_out;

    dim3 g1(2, 512);
    xproj_kernel<<<g1, 256>>>(x, Wih, bih, out);

    // 64 clusters x 2 CTAs, 1 batch per cluster
    rnn_scan_kernel<<<128, 256>>>(Whh, bhh, out);
}

// round 11
// speedup vs baseline: 1.6885x; 1.3892x over previous
#include <cuda_runtime.h>
#include <cstdint>
#include <math.h>

typedef unsigned long long u64;

// ---------------------------------------------------------------------------
// Packed f32x2 helpers (Blackwell sm_103a)
// ---------------------------------------------------------------------------
__device__ __forceinline__ u64 ffma2(u64 a, u64 b, u64 c) {
    u64 d;
    asm("fma.rn.f32x2 %0, %1, %2, %3;" : "=l"(d) : "l"(a), "l"(b), "l"(c));
    return d;
}
__device__ __forceinline__ u64 pack2(float x, float y) {
    u64 r;
    asm("mov.b64 %0, {%1, %2};" : "=l"(r) : "f"(x), "f"(y));
    return r;
}
__device__ __forceinline__ float2 unpack2(u64 v) {
    float2 f;
    asm("mov.b64 {%0, %1}, %2;" : "=f"(f.x), "=f"(f.y) : "l"(v));
    return f;
}
__device__ __forceinline__ uint32_t smem_u32(const void* p) {
    uint32_t a;
    asm("{ .reg .u64 t; cvta.to.shared.u64 t, %1; cvt.u32.u64 %0, t; }"
        : "=r"(a) : "l"(p));
    return a;
}

// Accurate tanh via ex2.approx (rel err ~2^-22); tanhf under fast-math lowers
// to tanh.approx (abs err ~2^-11) and fails 1e-3 over 1024 recurrent steps.
__device__ __forceinline__ float tanh_acc(float x) {
    float e = __expf(2.0f * x);
    return 1.0f - 2.0f / (e + 1.0f);
}

// ---------------------------------------------------------------------------
// Phase 1: x_proj GEMM with register-staged double buffering.
// Per k-stage, next stage's gmem float4s are prefetched into registers right
// after the store-sync, so the ~600cyc LDG latency hides under the ~1000cyc
// compute of the current stage (previously exposed every stage).
// ---------------------------------------------------------------------------
__global__ void __launch_bounds__(256) xproj_kernel(
    const float* __restrict__ X, const float* __restrict__ Wih,
    const float* __restrict__ bih, float* __restrict__ C)
{
    __shared__ __align__(16) float As[16][128];
    __shared__ __align__(16) float Bs[16][128];

    const int tid = threadIdx.x;
    const int tx  = tid & 15;
    const int ty  = tid >> 4;
    const int m0  = blockIdx.y * 128;
    const int n0  = blockIdx.x * 128;

    // per-thread load slots (2 A-quads + 2 B-quads per stage)
    int rowi[2], kqi[2];
#pragma unroll
    for (int i = 0; i < 2; i++) {
        int idx = tid + i * 256;
        rowi[i] = idx >> 2;
        kqi[i]  = (idx & 3) << 2;
    }

    u64 acc[8][4];
#pragma unroll
    for (int m = 0; m < 8; m++)
#pragma unroll
        for (int n = 0; n < 4; n++) acc[m][n] = 0ull;

    // prologue: stage 0 loads
    float4 xa[2], wa[2];
#pragma unroll
    for (int i = 0; i < 2; i++) {
        xa[i] = *(const float4*)(X   + (size_t)(m0 + rowi[i]) * 256 + kqi[i]);
        wa[i] = *(const float4*)(Wih + (size_t)(n0 + rowi[i]) * 256 + kqi[i]);
    }

    for (int k0i = 0; k0i < 16; k0i++) {
        __syncthreads();   // previous compute done: safe to overwrite buffers
#pragma unroll
        for (int i = 0; i < 2; i++) {
            As[kqi[i] + 0][rowi[i]] = xa[i].x; As[kqi[i] + 1][rowi[i]] = xa[i].y;
            As[kqi[i] + 2][rowi[i]] = xa[i].z; As[kqi[i] + 3][rowi[i]] = xa[i].w;
            Bs[kqi[i] + 0][rowi[i]] = wa[i].x; Bs[kqi[i] + 1][rowi[i]] = wa[i].y;
            Bs[kqi[i] + 2][rowi[i]] = wa[i].z; Bs[kqi[i] + 3][rowi[i]] = wa[i].w;
        }
        __syncthreads();

        // prefetch next stage while computing this one (latency hidden)
        if (k0i < 15) {
            int k0n = (k0i + 1) * 16;
#pragma unroll
            for (int i = 0; i < 2; i++) {
                xa[i] = *(const float4*)(X   + (size_t)(m0 + rowi[i]) * 256 + k0n + kqi[i]);
                wa[i] = *(const float4*)(Wih + (size_t)(n0 + rowi[i]) * 256 + k0n + kqi[i]);
            }
        }

#pragma unroll
        for (int kk = 0; kk < 16; kk++) {
            float4 a0 = *(const float4*)&As[kk][ty * 8];
            float4 a1 = *(const float4*)&As[kk][ty * 8 + 4];
            float4 b0 = *(const float4*)&Bs[kk][tx * 8];
            float4 b1 = *(const float4*)&Bs[kk][tx * 8 + 4];
            u64 bb[4] = { pack2(b0.x, b0.y), pack2(b0.z, b0.w),
                          pack2(b1.x, b1.y), pack2(b1.z, b1.w) };
            float am[8] = { a0.x, a0.y, a0.z, a0.w, a1.x, a1.y, a1.z, a1.w };
#pragma unroll
            for (int m = 0; m < 8; m++) {
                u64 ad = pack2(am[m], am[m]);
#pragma unroll
                for (int n = 0; n < 4; n++) acc[m][n] = ffma2(ad, bb[n], acc[m][n]);
            }
        }
    }

    const int nc = n0 + tx * 8;
    float4 bv0 = *(const float4*)(bih + nc);
    float4 bv1 = *(const float4*)(bih + nc + 4);
#pragma unroll
    for (int m = 0; m < 8; m++) {
        float2 r0 = unpack2(acc[m][0]), r1 = unpack2(acc[m][1]);
        float2 r2 = unpack2(acc[m][2]), r3 = unpack2(acc[m][3]);
        float* cp = C + (size_t)(m0 + ty * 8 + m) * 256 + nc;
        *(float4*)cp       = make_float4(r0.x + bv0.x, r0.y + bv0.y,
                                         r1.x + bv0.z, r1.y + bv0.w);
        *(float4*)(cp + 4) = make_float4(r2.x + bv1.x, r2.y + bv1.y,
                                         r3.x + bv1.z, r3.y + bv1.w);
    }
}

// ---------------------------------------------------------------------------
// Phase 2 (v11): "h-mirror" scan — X (DSMEM one-way latency) overlapped.
//
// Cluster of 2 CTAs per batch (64 clusters). CTA r owns outputs J_r.
// Threads tid 0..127  = A-warps (wid 0-3): output j = r*128+tid, k in J_r,
//   read h from LOCAL h_own. They combine, tanh, and SEND h to the peer.
// Threads tid 128..255 = B-warps (wid 4-7, hi-wid => arbiter PRIORITY):
//   same outputs, k in J_peer, read h from h_mir (peer-delivered mirror).
//
// Critical cycle: peer-A tanh -> st.async h (32 v4, 1 barrier) -> X ->
// B TRYWAIT wake -> B FMA (64 ffma2, priority) -> bar1 -> A combine
// (own partial computed DURING X) -> tanh -> send. A's FMA + xp prefetch
// hide under X, unlike R4 where X sat fully exposed after the joint FMA.
//
// mbar[q] guards mirror parity q (used at steps t with t&1==q); wait parity
// (t>>1)&1. Init: mbar[0] phase0 completed by a plain arrive (t=0 reads the
// pre-zeroed mirror); mbar[1] armed for t=1. B re-arms mbar[p] for t+2
// right after its wait and BEFORE bar1 => arm happens-before our A-send(t)
// happens-before peer's send landing for t+2 (R4 chain, deadlock-free).
// ---------------------------------------------------------------------------
__device__ __forceinline__ void mbar_wait_cluster(uint32_t addr, uint32_t parity) {
    asm volatile(
        "{\n\t"
        ".reg .pred P;\n\t"
        "LAB_W_%=:\n\t"
        "mbarrier.try_wait.parity.acquire.cluster.shared::cta.b64 P, [%0], %1, 0x989680;\n\t"
        "@P bra.uni LAB_D_%=;\n\t"
        "bra.uni LAB_W_%=;\n\t"
        "LAB_D_%=:\n\t"
        "}"
        :: "r"(addr), "r"(parity) : "memory");
}
__device__ __forceinline__ void mbar_expect(uint32_t addr, uint32_t bytes) {
    asm volatile("mbarrier.arrive.expect_tx.shared.b64 _, [%0], %1;"
                 :: "r"(addr), "r"(bytes) : "memory");
}
__device__ __forceinline__ void send_v4(uint32_t raddr, float s, float s1,
                                        float s2, float s3, uint32_t mbar) {
    asm volatile(
        "st.async.shared::cluster.mbarrier::complete_tx::bytes.v4.b32 "
        "[%0], {%1, %2, %3, %4}, [%5];"
        :: "r"(raddr),
           "r"(__float_as_uint(s)),  "r"(__float_as_uint(s1)),
           "r"(__float_as_uint(s2)), "r"(__float_as_uint(s3)),
           "r"(mbar) : "memory");
}

__global__ void __cluster_dims__(2, 1, 1) __launch_bounds__(256, 1)
rnn_scan_kernel(const float* __restrict__ Whh, const float* __restrict__ bhh,
                float* __restrict__ out)
{
    __shared__ __align__(16) float h_own[2][128];  // our h, written by A
    __shared__ __align__(16) float h_mir[2][128];  // peer h, delivered by st.async
    __shared__ __align__(16) float part[128];      // B partials (bar1-ordered)
    __shared__ __align__(16) u64 mbar[2];          // mirror-arrival barriers

    const int tid = threadIdx.x;
    uint32_t rank;
    asm("mov.u32 %0, %%cluster_ctarank;" : "=r"(rank));
    const int  batch = blockIdx.x >> 1;
    const int  jl    = tid & 127;
    const bool isB   = (tid >= 128);            // remote-k warps (hi-wid priority)
    const int  j     = (int)rank * 128 + jl;    // output index (both roles)
    const int  kbase = isB ? ((int)(rank ^ 1u) * 128) : ((int)rank * 128);

    // --- W_hh[j][kbase .. kbase+127] -> 64 packed f32x2 registers ---
    u64 w2[64];
    {
        const ulonglong2* wrow = (const ulonglong2*)(Whh + (size_t)j * 256 + kbase);
#pragma unroll
        for (int i = 0; i < 32; i++) {
            ulonglong2 v = wrow[i];
            w2[2 * i] = v.x; w2[2 * i + 1] = v.y;
        }
    }

    // --- init ---
    if (tid < 128) {
        h_own[0][tid] = 0.0f; h_own[1][tid] = 0.0f;
        h_mir[0][tid] = 0.0f; h_mir[1][tid] = 0.0f;   // h_0 = 0 for t=0
    }
    uint32_t mbar_a0 = smem_u32(&mbar[0]);
    uint32_t mbar_a1 = smem_u32(&mbar[1]);
    if (tid == 0) {
        asm volatile("mbarrier.init.shared.b64 [%0], 1;" :: "r"(mbar_a0) : "memory");
        asm volatile("mbarrier.init.shared.b64 [%0], 1;" :: "r"(mbar_a1) : "memory");
    }
    __syncthreads();
    if (tid == 0) {
        // mbar[0]: complete phase 0 now — t=0 reads the pre-zeroed mirror
        asm volatile("mbarrier.arrive.shared.b64 _, [%0];" :: "r"(mbar_a0) : "memory");
        // mbar[1]: armed for peer h(1) arriving for t=1
        mbar_expect(mbar_a1, 512u);
    }
    asm volatile("barrier.cluster.arrive.aligned;" ::: "memory");
    asm volatile("barrier.cluster.wait.aligned;" ::: "memory");

    uint32_t mir_a = smem_u32(&h_mir[0][0]);
    uint32_t peer = rank ^ 1u;
    uint32_t mir_peer, mbar_peer_base;
    asm("mapa.shared::cluster.u32 %0, %1, %2;" : "=r"(mir_peer)       : "r"(mir_a),   "r"(peer));
    asm("mapa.shared::cluster.u32 %0, %1, %2;" : "=r"(mbar_peer_base) : "r"(mbar_a0), "r"(peer));

    float* outb = out + (size_t)batch * (1024 * 256) + j;   // column j
    const float bh = bhh[j];
    float xp_next = isB ? 0.0f : outb[0];

    if (isB) {
        // ================= B role: remote-k partial producer =================
        for (int t = 0; t < 1024; t++) {
            const uint32_t p = (uint32_t)(t & 1);
            const uint32_t mb = p ? mbar_a1 : mbar_a0;
            mbar_wait_cluster(mb, (uint32_t)((t >> 1) & 1));
            // re-arm for t+2 BEFORE bar1: orders arm < our A-send(t) < peer
            // send landing for t+2 (deadlock/underflow-free, R4 chain)
            if (jl == 0 && t < 1022) mbar_expect(mb, 512u);

            const ulonglong2* h4 = (const ulonglong2*)&h_mir[p][0];
            u64 acc0 = 0ull, acc1 = 0ull;
#pragma unroll
            for (int i = 0; i < 16; i++) {
                ulonglong2 va = h4[2 * i];
                acc0 = ffma2(w2[4 * i],     va.x, acc0);
                acc1 = ffma2(w2[4 * i + 1], va.y, acc1);
                ulonglong2 vb = h4[2 * i + 1];
                acc0 = ffma2(w2[4 * i + 2], vb.x, acc0);
                acc1 = ffma2(w2[4 * i + 3], vb.y, acc1);
            }
            float2 a0 = unpack2(acc0), a1 = unpack2(acc1);
            part[jl] = (a0.x + a0.y) + (a1.x + a1.y);
            asm volatile("bar.sync 1, 256;" ::: "memory");   // partial ready
        }
    } else {
        // ================= A role: own-k FMA + combine + send ================
        for (int t = 0; t < 1024; t++) {
            const uint32_t p = (uint32_t)(t & 1);

            // own-k partial: runs DURING the peer->B transit window
            const ulonglong2* h4 = (const ulonglong2*)&h_own[p][0];
            u64 acc0 = 0ull, acc1 = 0ull;
#pragma unroll
            for (int i = 0; i < 16; i++) {
                ulonglong2 va = h4[2 * i];
                acc0 = ffma2(w2[4 * i],     va.x, acc0);
                acc1 = ffma2(w2[4 * i + 1], va.y, acc1);
                ulonglong2 vb = h4[2 * i + 1];
                acc0 = ffma2(w2[4 * i + 2], vb.x, acc0);
                acc1 = ffma2(w2[4 * i + 3], vb.y, acc1);
            }
            float2 a0 = unpack2(acc0), a1 = unpack2(acc1);
            const float s = (a0.x + a0.y) + (a1.x + a1.y);

            const float xp_cur = xp_next;
            if (t < 1023) xp_next = __ldg(outb + (size_t)(t + 1) * 256);

            asm volatile("bar.sync 1, 256;" ::: "memory");   // B's partial ready

            const float tot = s + part[jl] + xp_cur + bh;
            const float h = tanh_acc(tot);
            h_own[p ^ 1][jl] = h;

            // send h(t+1) to peer mirror[p^1] ASAP (critical path)
            if (t < 1023) {
                const float u1 = __shfl_down_sync(0xFFFFFFFFu, h, 1);
                const float u2 = __shfl_down_sync(0xFFFFFFFFu, h, 2);
                const float u3 = __shfl_down_sync(0xFFFFFFFFu, h, 3);
                if ((tid & 3) == 0)
                    send_v4(mir_peer + (((p ^ 1u) << 9) | ((uint32_t)jl << 2)),
                            h, u1, u2, u3,
                            mbar_peer_base + ((p ^ 1u) << 3));
            }
            outb[(size_t)t * 256] = h;

            asm volatile("bar.sync 2, 128;" ::: "memory");   // A-only: h_own visible
        }
    }

    // keep smem alive until peer's in-flight st.async complete
    asm volatile("barrier.cluster.arrive.aligned;" ::: "memory");
    asm volatile("barrier.cluster.wait.aligned;" ::: "memory");
}

// ---------------------------------------------------------------------------
// Harness entry. Inputs: x, W_ih, W_hh, b_ih, b_hh. Output fp32 [B,T,H].
// x_proj is materialized into d_out, then overwritten in place by h_t.
// ---------------------------------------------------------------------------
extern "C" void kernel_launch(void* const* d_in, const int* in_sizes, int n_in,
                              void* d_out, int out_size)
{
    const float* x   = (const float*)d_in[0];
    const float* Wih = (const float*)d_in[1];
    const float* Whh = (const float*)d_in[2];
    const float* bih = (const float*)d_in[3];
    const float* bhh = (const float*)d_in[4];
    float* out = (float*)d_out;

    dim3 g1(2, 512);
    xproj_kernel<<<g1, 256>>>(x, Wih, bih, out);

    // 64 clusters x 2 CTAs, 1 batch per cluster
    rnn_scan_kernel<<<128, 256>>>(Whh, bhh, out);
}

// round 13
// speedup vs baseline: 1.7910x; 1.0607x over previous
#include <cuda_runtime.h>
#include <cuda_bf16.h>
#include <cstdint>
#include <math.h>

typedef unsigned long long u64;

// ---------------------------------------------------------------------------
// Packed f32x2 helpers (Blackwell sm_103a)
// ---------------------------------------------------------------------------
__device__ __forceinline__ u64 ffma2(u64 a, u64 b, u64 c) {
    u64 d;
    asm("fma.rn.f32x2 %0, %1, %2, %3;" : "=l"(d) : "l"(a), "l"(b), "l"(c));
    return d;
}
__device__ __forceinline__ float2 unpack2(u64 v) {
    float2 f;
    asm("mov.b64 {%0, %1}, %2;" : "=f"(f.x), "=f"(f.y) : "l"(v));
    return f;
}
__device__ __forceinline__ uint32_t smem_u32(const void* p) {
    uint32_t a;
    asm("{ .reg .u64 t; cvta.to.shared.u64 t, %1; cvt.u32.u64 %0, t; }"
        : "=r"(a) : "l"(p));
    return a;
}

// Accurate tanh via ex2.approx (rel err ~2^-22); tanhf under fast-math lowers
// to tanh.approx (abs err ~2^-11) and fails 1e-3 over 1024 recurrent steps.
__device__ __forceinline__ float tanh_acc(float x) {
    float e = __expf(2.0f * x);
    return 1.0f - 2.0f / (e + 1.0f);
}

// ---------------------------------------------------------------------------
// Phase 1 (v3): warp-level mma.sync bf16-split GEMM (compute_103-safe).
// C[m][n] = x[m,:]·W[n,:] + b[n];  D = xh·Wh + xh·Wl + xl·Wh (fp32 accum).
//
// Per CTA: 128x128 output, K = 256 in 2 chunks of 128. fp32 tiles are loaded
// from gmem and split to bf16 hi/lo INLINE during the smem store (no scratch,
// no prep kernels). Tiles are XOR-swizzled (k2 ^ ((row&7)<<4)) -> conflict-
// free ldmatrix. 8 warps = 2(M) x 4(N); warp tile 64x32; 3 HMMA per k16 tile.
//
// Fragment layouts (PTX ISA m16n8k16 .bf16):
//   A: ldmatrix.x4, lane addr row = l&15, k-half = l>>4
//      -> r0..r3 = (m0-7,k0-7),(m8-15,k0-7),(m0-7,k8-15),(m8-15,k8-15) = a0..a3
//   B: ldmatrix.x2 on K-major W rows: lane addr n-row = l&7, k-half = (l>>3)&1
//      -> b0 = k0-7, b1 = k8-15 with lane l holding (k=2(l%4)+{0,1}, n=l/4)
//   D: d0/d1 = (row=l/4, col=2(l%4)+{0,1}), d2/d3 = row+8.
// ---------------------------------------------------------------------------
#define XP_AH 0
#define XP_AL (128 * 256)
#define XP_BH (2 * 128 * 256)
#define XP_BL (3 * 128 * 256)
#define XP_SMEM_TOTAL (4 * 128 * 256)   // 131072 bytes

__device__ __forceinline__ void ldsm_x4(uint32_t& r0, uint32_t& r1,
                                        uint32_t& r2, uint32_t& r3, uint32_t a) {
    asm volatile("ldmatrix.sync.aligned.m8n8.x4.shared.b16 {%0,%1,%2,%3}, [%4];"
                 : "=r"(r0), "=r"(r1), "=r"(r2), "=r"(r3) : "r"(a));
}
__device__ __forceinline__ void ldsm_x2(uint32_t& r0, uint32_t& r1, uint32_t a) {
    asm volatile("ldmatrix.sync.aligned.m8n8.x2.shared.b16 {%0,%1}, [%2];"
                 : "=r"(r0), "=r"(r1) : "r"(a));
}
__device__ __forceinline__ void mma_bf16(float* d, const uint32_t* a,
                                         const uint32_t* b) {
    asm volatile(
        "mma.sync.aligned.m16n8k16.row.col.f32.bf16.bf16.f32 "
        "{%0,%1,%2,%3}, {%4,%5,%6,%7}, {%8,%9}, {%0,%1,%2,%3};"
        : "+f"(d[0]), "+f"(d[1]), "+f"(d[2]), "+f"(d[3])
        : "r"(a[0]), "r"(a[1]), "r"(a[2]), "r"(a[3]), "r"(b[0]), "r"(b[1]));
}
__device__ __forceinline__ u64 pack_bf16x4(float a, float b, float c, float d,
                                           bool lo) {
    __nv_bfloat16 h0 = __float2bfloat16_rn(a), h1 = __float2bfloat16_rn(b);
    __nv_bfloat16 h2 = __float2bfloat16_rn(c), h3 = __float2bfloat16_rn(d);
    if (lo) {
        h0 = __float2bfloat16_rn(a - __bfloat162float(h0));
        h1 = __float2bfloat16_rn(b - __bfloat162float(h1));
        h2 = __float2bfloat16_rn(c - __bfloat162float(h2));
        h3 = __float2bfloat16_rn(d - __bfloat162float(h3));
    }
    return (u64)__bfloat16_as_ushort(h0)
         | ((u64)__bfloat16_as_ushort(h1) << 16)
         | ((u64)__bfloat16_as_ushort(h2) << 32)
         | ((u64)__bfloat16_as_ushort(h3) << 48);
}

// load a 128x128 fp32 block (k-chunk kc of a 256-wide row-major src) and
// store bf16 hi/lo split into swizzled smem tiles
__device__ __forceinline__ void load_split_tile(char* sm, int base_h, int base_l,
                                                const float* src, int kc, int tid) {
    for (int idx = tid; idx < 128 * 32; idx += 256) {
        int row = idx >> 5;
        int c4  = (idx & 31) << 2;          // k index within chunk, 0..124
        float4 v = *(const float4*)(src + (size_t)row * 256 + kc * 128 + c4);
        uint32_t byte = (uint32_t)(row * 256 + ((c4 * 2) ^ ((row & 7) << 4)));
        *(u64*)(sm + base_h + byte) = pack_bf16x4(v.x, v.y, v.z, v.w, false);
        *(u64*)(sm + base_l + byte) = pack_bf16x4(v.x, v.y, v.z, v.w, true);
    }
}

__global__ void __launch_bounds__(256, 1)
xproj_mma_kernel(const float* __restrict__ X, const float* __restrict__ Wih,
                 const float* __restrict__ bih, float* __restrict__ C)
{
    extern __shared__ __align__(16) char sm[];
    const int tid  = threadIdx.x;
    const int lane = tid & 31;
    const int wid  = tid >> 5;
    const int wm   = wid & 1;            // 2 M-warps x 64 rows
    const int wn   = wid >> 1;           // 4 N-warps x 32 cols
    const int m0   = blockIdx.x * 128;
    const int n0   = blockIdx.y * 128;
    const uint32_t smb = smem_u32(sm);

    float d[4][4][4];                    // [mi][ni][reg]
#pragma unroll
    for (int mi = 0; mi < 4; mi++)
#pragma unroll
        for (int ni = 0; ni < 4; ni++)
#pragma unroll
            for (int r = 0; r < 4; r++) d[mi][ni][r] = 0.0f;

    // lane-invariant address components
    const int a_row_l  = (lane & 15);
    const int a_half   = (lane >> 4) * 16;        // bytes
    const int b_row_l  = (lane & 7);
    const int b_half   = ((lane >> 3) & 1) * 16;  // bytes

    for (int kc = 0; kc < 2; kc++) {
        __syncthreads();    // previous chunk's ldmatrix reads complete
        load_split_tile(sm, XP_AH, XP_AL, X   + (size_t)m0 * 256, kc, tid);
        load_split_tile(sm, XP_BH, XP_BL, Wih + (size_t)n0 * 256, kc, tid);
        __syncthreads();

#pragma unroll
        for (int kk = 0; kk < 8; kk++) {
            const int kb = kk * 32;      // 16 bf16 = 32 bytes
            uint32_t ah[4][4], al[4][4], bh[4][2], bl[4][2];
#pragma unroll
            for (int mi = 0; mi < 4; mi++) {
                int row = wm * 64 + mi * 16 + a_row_l;
                uint32_t byte = (uint32_t)(row * 256
                               + ((kb + a_half) ^ ((row & 7) << 4)));
                ldsm_x4(ah[mi][0], ah[mi][1], ah[mi][2], ah[mi][3],
                        smb + XP_AH + byte);
                ldsm_x4(al[mi][0], al[mi][1], al[mi][2], al[mi][3],
                        smb + XP_AL + byte);
            }
#pragma unroll
            for (int ni = 0; ni < 4; ni++) {
                int nrow = wn * 32 + ni * 8 + b_row_l;
                uint32_t byte = (uint32_t)(nrow * 256
                               + ((kb + b_half) ^ ((nrow & 7) << 4)));
                ldsm_x2(bh[ni][0], bh[ni][1], smb + XP_BH + byte);
                ldsm_x2(bl[ni][0], bl[ni][1], smb + XP_BL + byte);
            }
#pragma unroll
            for (int mi = 0; mi < 4; mi++)
#pragma unroll
                for (int ni = 0; ni < 4; ni++) {
                    mma_bf16(d[mi][ni], ah[mi], bh[ni]);   // xh*Wh
                    mma_bf16(d[mi][ni], ah[mi], bl[ni]);   // xh*Wl
                    mma_bf16(d[mi][ni], al[mi], bh[ni]);   // xl*Wh
                }
        }
    }

    // epilogue: direct float2 stores + bias
#pragma unroll
    for (int ni = 0; ni < 4; ni++) {
        const int ncol = n0 + wn * 32 + ni * 8 + (lane & 3) * 2;
        const float2 bv = *(const float2*)(bih + ncol);
#pragma unroll
        for (int mi = 0; mi < 4; mi++) {
            const int mrow = m0 + wm * 64 + mi * 16 + (lane >> 2);
            float2 v0 = make_float2(d[mi][ni][0] + bv.x, d[mi][ni][1] + bv.y);
            float2 v1 = make_float2(d[mi][ni][2] + bv.x, d[mi][ni][3] + bv.y);
            *(float2*)(C + (size_t)mrow * 256 + ncol)       = v0;
            *(float2*)(C + (size_t)(mrow + 8) * 256 + ncol) = v1;
        }
    }
}

// ---------------------------------------------------------------------------
// Phase 2 (v11, UNCHANGED R11 winner): h-mirror scan, X overlapped.
// ---------------------------------------------------------------------------
__device__ __forceinline__ void mbar_wait_cluster(uint32_t addr, uint32_t parity) {
    asm volatile(
        "{\n\t"
        ".reg .pred P;\n\t"
        "LAB_W_%=:\n\t"
        "mbarrier.try_wait.parity.acquire.cluster.shared::cta.b64 P, [%0], %1, 0x989680;\n\t"
        "@P bra.uni LAB_D_%=;\n\t"
        "bra.uni LAB_W_%=;\n\t"
        "LAB_D_%=:\n\t"
        "}"
        :: "r"(addr), "r"(parity) : "memory");
}
__device__ __forceinline__ void mbar_expect(uint32_t addr, uint32_t bytes) {
    asm volatile("mbarrier.arrive.expect_tx.shared.b64 _, [%0], %1;"
                 :: "r"(addr), "r"(bytes) : "memory");
}
__device__ __forceinline__ void send_v4(uint32_t raddr, float s, float s1,
                                        float s2, float s3, uint32_t mbar) {
    asm volatile(
        "st.async.shared::cluster.mbarrier::complete_tx::bytes.v4.b32 "
        "[%0], {%1, %2, %3, %4}, [%5];"
        :: "r"(raddr),
           "r"(__float_as_uint(s)),  "r"(__float_as_uint(s1)),
           "r"(__float_as_uint(s2)), "r"(__float_as_uint(s3)),
           "r"(mbar) : "memory");
}

__global__ void __cluster_dims__(2, 1, 1) __launch_bounds__(256, 1)
rnn_scan_kernel(const float* __restrict__ Whh, const float* __restrict__ bhh,
                float* __restrict__ out)
{
    __shared__ __align__(16) float h_own[2][128];
    __shared__ __align__(16) float h_mir[2][128];
    __shared__ __align__(16) float part[128];
    __shared__ __align__(16) u64 mbar[2];

    const int tid = threadIdx.x;
    uint32_t rank;
    asm("mov.u32 %0, %%cluster_ctarank;" : "=r"(rank));
    const int  batch = blockIdx.x >> 1;
    const int  jl    = tid & 127;
    const bool isB   = (tid >= 128);
    const int  j     = (int)rank * 128 + jl;
    const int  kbase = isB ? ((int)(rank ^ 1u) * 128) : ((int)rank * 128);

    u64 w2[64];
    {
        const ulonglong2* wrow = (const ulonglong2*)(Whh + (size_t)j * 256 + kbase);
#pragma unroll
        for (int i = 0; i < 32; i++) {
            ulonglong2 v = wrow[i];
            w2[2 * i] = v.x; w2[2 * i + 1] = v.y;
        }
    }

    if (tid < 128) {
        h_own[0][tid] = 0.0f; h_own[1][tid] = 0.0f;
        h_mir[0][tid] = 0.0f; h_mir[1][tid] = 0.0f;
    }
    uint32_t mbar_a0 = smem_u32(&mbar[0]);
    uint32_t mbar_a1 = smem_u32(&mbar[1]);
    if (tid == 0) {
        asm volatile("mbarrier.init.shared.b64 [%0], 1;" :: "r"(mbar_a0) : "memory");
        asm volatile("mbarrier.init.shared.b64 [%0], 1;" :: "r"(mbar_a1) : "memory");
    }
    __syncthreads();
    if (tid == 0) {
        asm volatile("mbarrier.arrive.shared.b64 _, [%0];" :: "r"(mbar_a0) : "memory");
        mbar_expect(mbar_a1, 512u);
    }
    asm volatile("barrier.cluster.arrive.aligned;" ::: "memory");
    asm volatile("barrier.cluster.wait.aligned;" ::: "memory");

    uint32_t mir_a = smem_u32(&h_mir[0][0]);
    uint32_t peer = rank ^ 1u;
    uint32_t mir_peer, mbar_peer_base;
    asm("mapa.shared::cluster.u32 %0, %1, %2;" : "=r"(mir_peer)       : "r"(mir_a),   "r"(peer));
    asm("mapa.shared::cluster.u32 %0, %1, %2;" : "=r"(mbar_peer_base) : "r"(mbar_a0), "r"(peer));

    float* outb = out + (size_t)batch * (1024 * 256) + j;
    const float bh = bhh[j];
    float xp_next = isB ? 0.0f : outb[0];

    if (isB) {
        for (int t = 0; t < 1024; t++) {
            const uint32_t p = (uint32_t)(t & 1);
            const uint32_t mb = p ? mbar_a1 : mbar_a0;
            mbar_wait_cluster(mb, (uint32_t)((t >> 1) & 1));
            if (jl == 0 && t < 1022) mbar_expect(mb, 512u);

            const ulonglong2* h4 = (const ulonglong2*)&h_mir[p][0];
            u64 acc0 = 0ull, acc1 = 0ull;
#pragma unroll
            for (int i = 0; i < 16; i++) {
                ulonglong2 va = h4[2 * i];
                acc0 = ffma2(w2[4 * i],     va.x, acc0);
                acc1 = ffma2(w2[4 * i + 1], va.y, acc1);
                ulonglong2 vb = h4[2 * i + 1];
                acc0 = ffma2(w2[4 * i + 2], vb.x, acc0);
                acc1 = ffma2(w2[4 * i + 3], vb.y, acc1);
            }
            float2 a0 = unpack2(acc0), a1 = unpack2(acc1);
            part[jl] = (a0.x + a0.y) + (a1.x + a1.y);
            asm volatile("bar.sync 1, 256;" ::: "memory");
        }
    } else {
        for (int t = 0; t < 1024; t++) {
            const uint32_t p = (uint32_t)(t & 1);

            const ulonglong2* h4 = (const ulonglong2*)&h_own[p][0];
            u64 acc0 = 0ull, acc1 = 0ull;
#pragma unroll
            for (int i = 0; i < 16; i++) {
                ulonglong2 va = h4[2 * i];
                acc0 = ffma2(w2[4 * i],     va.x, acc0);
                acc1 = ffma2(w2[4 * i + 1], va.y, acc1);
                ulonglong2 vb = h4[2 * i + 1];
                acc0 = ffma2(w2[4 * i + 2], vb.x, acc0);
                acc1 = ffma2(w2[4 * i + 3], vb.y, acc1);
            }
            float2 a0 = unpack2(acc0), a1 = unpack2(acc1);
            const float s = (a0.x + a0.y) + (a1.x + a1.y);

            const float xp_cur = xp_next;
            if (t < 1023) xp_next = __ldg(outb + (size_t)(t + 1) * 256);

            asm volatile("bar.sync 1, 256;" ::: "memory");

            const float tot = s + part[jl] + xp_cur + bh;
            const float h = tanh_acc(tot);
            h_own[p ^ 1][jl] = h;

            if (t < 1023) {
                const float u1 = __shfl_down_sync(0xFFFFFFFFu, h, 1);
                const float u2 = __shfl_down_sync(0xFFFFFFFFu, h, 2);
                const float u3 = __shfl_down_sync(0xFFFFFFFFu, h, 3);
                if ((tid & 3) == 0)
                    send_v4(mir_peer + (((p ^ 1u) << 9) | ((uint32_t)jl << 2)),
                            h, u1, u2, u3,
                            mbar_peer_base + ((p ^ 1u) << 3));
            }
            outb[(size_t)t * 256] = h;

            asm volatile("bar.sync 2, 128;" ::: "memory");
        }
    }

    asm volatile("barrier.cluster.arrive.aligned;" ::: "memory");
    asm volatile("barrier.cluster.wait.aligned;" ::: "memory");
}

// ---------------------------------------------------------------------------
// Harness entry. Inputs: x, W_ih, W_hh, b_ih, b_hh. Output fp32 [B,T,H].
// x_proj (mma.sync bf16-split GEMM) lands in d_out; scan overwrites it.
// ---------------------------------------------------------------------------
extern "C" void kernel_launch(void* const* d_in, const int* in_sizes, int n_in,
                              void* d_out, int out_size)
{
    const float* x   = (const float*)d_in[0];
    const float* Wih = (const float*)d_in[1];
    const float* Whh = (const float*)d_in[2];
    const float* bih = (const float*)d_in[3];
    const float* bhh = (const float*)d_in[4];
    float* out = (float*)d_out;

    static bool attr_set = false;
    if (!attr_set) {
        cudaFuncSetAttribute(xproj_mma_kernel,
                             cudaFuncAttributeMaxDynamicSharedMemorySize,
                             XP_SMEM_TOTAL);
        attr_set = true;
    }

    // Phase 1: tensor-core x_proj GEMM (512 M-tiles x 2 N-tiles)
    dim3 gg(512, 2);
    xproj_mma_kernel<<<gg, 256, XP_SMEM_TOTAL>>>(x, Wih, bih, out);

    // Phase 2: recurrent scan (64 clusters x 2 CTAs)
    rnn_scan_kernel<<<128, 256>>>(Whh, bhh, out);
}